// round 15
// baseline (speedup 1.0000x reference)
#include <cuda_runtime.h>
#include <math.h>

#define Bz   64
#define Nn   512
#define Ez   8192
#define NWd  16      // bitmap words per row (512/32)
#define Dd   16
#define Kk   16
#define NBINS 16

// ---------------- scratch (static device allocations) ----------------
__device__ unsigned g_bm[2][Bz][Nn][NWd];        // adjacency bitmaps (4 MB)
__device__ float    g_dinv[2][Bz][Nn];           // D^-1/2
__device__ float    g_bufA[2][Bz * Nn * 64];     // ping  (16.8 MB)
__device__ float    g_bufB[2][Bz * Nn * 64];     // pong  (16.8 MB)
__device__ float    g_u[2][Bz][Nn][Dd];          // final node embeddings
__device__ float    g_h[2][Bz][Dd];              // pooled graph embeddings
__device__ unsigned g_mm[Bz][2];                 // encoded {min,max} of raw dots
__device__ float    g_thr[Bz][16];               // 15 bin thresholds in dot space
__device__ int      g_hist[Bz][NBINS];
__device__ float    g_inter[Bz][Kk];             // NTN interaction

// monotone float <-> uint mapping for atomicMin/Max over signed floats
__device__ __forceinline__ unsigned enc_f(float f) {
    unsigned u = __float_as_uint(f);
    return (u & 0x80000000u) ? ~u : (u | 0x80000000u);
}
__device__ __forceinline__ float dec_f(unsigned e) {
    return (e & 0x80000000u) ? __uint_as_float(e & 0x7FFFFFFFu)
                             : __uint_as_float(~e);
}

// Reference fp32 sigmoid, exp form with correctly-rounded exp:
// s = RN(1 / RN(1 + RN(e^-x))). At |x| ~ 1e-6 both Eigen pexp (CPU XLA) and
// a CR exp agree; reproduce via double exp + fp32 round. IEEE chain forced.
__device__ __forceinline__ float sig_ref(float x) {
    float e = (float)exp(-(double)x);
    return __fdiv_rn(1.0f, __fadd_rn(1.0f, e));
}

// Reference binning with XLA's divide->reciprocal-multiply rewrite:
//   recip = RN(1/denom)  (computed once per graph)
//   idx = clip(trunc(RN(RN(s-mn) * recip) * 16), 0, 15)
// The *16 is an exact power-of-2 scaling (fold order bit-neutral).
__device__ __forceinline__ int bin_of(float s, float mn, float recip) {
    float t = __fsub_rn(s, mn);
    float q = __fmul_rn(t, recip);
    float v = q * 16.0f;              // exact scaling, no rounding
    int ix = (int)v;
    return ix < 0 ? 0 : (ix > 15 ? 15 : ix);
}

// ---------------- init: zero bitmaps + hist, init min/max ----------------
__global__ void k_init() {
    int idx = blockIdx.x * blockDim.x + threadIdx.x;
    unsigned* bm = &g_bm[0][0][0][0];
    const int total = 2 * Bz * Nn * NWd;   // 1,048,576
    for (int i = idx; i < total; i += gridDim.x * blockDim.x) bm[i] = 0u;
    if (idx < Bz * NBINS) ((int*)g_hist)[idx] = 0;
    if (idx < Bz) { g_mm[idx][0] = 0xFFFFFFFFu; g_mm[idx][1] = 0u; }
}

// ---------------- scatter edges + self loops into bitmaps ----------------
__global__ void k_scatter(const int* __restrict__ ei, const int* __restrict__ ej) {
    int idx = blockIdx.x * blockDim.x + threadIdx.x;
    const int TE = 2 * Bz * Ez;
    if (idx < TE) {
        int side = idx / (Bz * Ez);
        int rem  = idx - side * (Bz * Ez);
        int b = rem / Ez, e = rem - (rem / Ez) * Ez;
        const int* p = side ? ej : ei;
        int r = p[(size_t)b * 2 * Ez + e];
        int c = p[(size_t)b * 2 * Ez + Ez + e];
        atomicOr(&g_bm[side][b][r][c >> 5], 1u << (c & 31));
    } else {
        int j = idx - TE;
        if (j < 2 * Bz * Nn) {
            int side = j / (Bz * Nn);
            int rem  = j - side * (Bz * Nn);
            int b = rem >> 9, n = rem & 511;
            atomicOr(&g_bm[side][b][n][n >> 5], 1u << (n & 31));
        }
    }
}

// ---------------- degrees -> D^-1/2 (correctly rounded via double) --------
__global__ void k_dinv() {
    int idx = blockIdx.x * blockDim.x + threadIdx.x;  // 2*Bz*Nn threads
    int side = idx >> 15;
    int rem  = idx & 32767;
    int b = rem >> 9, n = rem & 511;
    unsigned deg = 0;
#pragma unroll
    for (int w = 0; w < NWd; w++) deg += __popc(g_bm[side][b][n][w]);
    g_dinv[side][b][n] = (float)(1.0 / sqrt((double)deg));   // deg >= 1
}

// ---------------- dense GEMM: Y[M,NC] = X[M,KK] @ W[KK,NC] ----------------
// fp32, sequential ascending-k FMA chain per output (Eigen/cublas-SIMT order).
template<int KK, int NC>
__global__ void k_gemm(const float* __restrict__ X, const float* __restrict__ W,
                       float* __restrict__ Y) {
    __shared__ float Ws[KK * NC];
    __shared__ float Xs[16][KK + 2];
    const int NT = NC * 2;
    int tid = threadIdx.x;
    int r0  = blockIdx.x * 16;
    for (int i = tid; i < KK * NC; i += NT) Ws[i] = W[i];
    for (int i = tid; i < 16 * KK; i += NT) {
        int r = i / KK, k = i - r * KK;
        Xs[r][k] = X[(size_t)(r0 + r) * KK + k];
    }
    __syncthreads();
    int cp  = tid % (NC / 2);
    int rg  = tid / (NC / 2);       // 0..3
    int col = cp * 2;
    float2 a0 = {0.f,0.f}, a1 = {0.f,0.f}, a2 = {0.f,0.f}, a3 = {0.f,0.f};
#pragma unroll 8
    for (int k = 0; k < KK; k++) {
        float2 wv = *(const float2*)&Ws[k * NC + col];
        float x0 = Xs[rg * 4 + 0][k];
        float x1 = Xs[rg * 4 + 1][k];
        float x2 = Xs[rg * 4 + 2][k];
        float x3 = Xs[rg * 4 + 3][k];
        a0.x += x0 * wv.x; a0.y += x0 * wv.y;
        a1.x += x1 * wv.x; a1.y += x1 * wv.y;
        a2.x += x2 * wv.x; a2.y += x2 * wv.y;
        a3.x += x3 * wv.x; a3.y += x3 * wv.y;
    }
    size_t base = (size_t)(r0 + rg * 4) * NC + col;
    *(float2*)&Y[base]          = a0;
    *(float2*)&Y[base + NC]     = a1;
    *(float2*)&Y[base + 2 * NC] = a2;
    *(float2*)&Y[base + 3 * NC] = a3;
}

// ---------------- SpMM: Y = act(D^-1/2 (A+I) D^-1/2 @ X + bias) ------------
// Ascending-c sparse accumulation == dense sequential fp32 chain bitwise
// (skipping exact-zero terms in an FMA chain is a no-op).
template<int FO, bool RELU>
__global__ void k_spmm(int side, const float* __restrict__ Xin,
                       const float* __restrict__ bias, float* __restrict__ Y) {
    extern __shared__ float sm[];
    float* sx = sm;              // Nn*FO
    float* sd = sm + Nn * FO;    // Nn
    int b   = blockIdx.x;
    int tid = threadIdx.x;       // 512
    const float* xin = Xin + (size_t)b * Nn * FO;
    for (int i = tid; i < Nn * FO / 4; i += 512)
        ((float4*)sx)[i] = ((const float4*)xin)[i];
    for (int i = tid; i < Nn; i += 512) sd[i] = g_dinv[side][b][i];
    __syncthreads();
    int warp = tid >> 5, lane = tid & 31;
    for (int r = warp; r < Nn; r += 16) {
        const unsigned* bmrow = g_bm[side][b][r];
        float dr = sd[r];
        float2 acc = make_float2(0.f, 0.f);
#pragma unroll
        for (int w = 0; w < NWd; w++) {
            unsigned bits = bmrow[w];
            while (bits) {
                int t = __ffs(bits) - 1; bits &= bits - 1;
                int c = (w << 5) + t;
                float coef = __fmul_rn(dr, sd[c]);
                if (lane * 2 < FO) {
                    float2 v = *(const float2*)&sx[c * FO + lane * 2];
                    acc.x += coef * v.x; acc.y += coef * v.y;
                }
            }
        }
        if (lane * 2 < FO) {
            float vx = acc.x + bias[lane * 2];
            float vy = acc.y + bias[lane * 2 + 1];
            if (RELU) { vx = fmaxf(vx, 0.f); vy = fmaxf(vy, 0.f); }
            *(float2*)&Y[((size_t)b * Nn + r) * FO + lane * 2] = make_float2(vx, vy);
        }
    }
}

// ---------------- attention pooling (fp32; low output weight) ---------------
__global__ void k_attpool(const float* __restrict__ attn_w) {
    __shared__ float s_mean[Dd], s_c[Dd], s_h[Dd];
    int side = blockIdx.x >> 6;     // 128 blocks: 2 sides x 64 graphs
    int b    = blockIdx.x & 63;
    int tid  = threadIdx.x;          // 256
    if (tid < Dd) { s_mean[tid] = 0.f; s_h[tid] = 0.f; }
    __syncthreads();
    const float* u = &g_u[side][b][0][0];
    float loc[Dd];
#pragma unroll
    for (int d = 0; d < Dd; d++) loc[d] = u[tid * Dd + d] + u[(tid + 256) * Dd + d];
#pragma unroll
    for (int d = 0; d < Dd; d++) atomicAdd(&s_mean[d], loc[d]);
    __syncthreads();
    if (tid < Dd) {
        float acc = 0.f;
#pragma unroll
        for (int e = 0; e < Dd; e++)
            acc += (s_mean[e] * (1.f / (float)Nn)) * attn_w[e * Dd + tid];
        s_c[tid] = tanhf(acc);
    }
    __syncthreads();
    for (int pass = 0; pass < 2; pass++) {
        int n = tid + pass * 256;
        float uv[Dd];
        float dot = 0.f;
#pragma unroll
        for (int d = 0; d < Dd; d++) { uv[d] = u[n * Dd + d]; dot += uv[d] * s_c[d]; }
        float s = 1.f / (1.f + expf(-dot));
#pragma unroll
        for (int d = 0; d < Dd; d++) atomicAdd(&s_h[d], s * uv[d]);
    }
    __syncthreads();
    if (tid < Dd) g_h[side][b][tid] = s_h[tid];
}

// ---------------- NTN (fp32) ----------------
__global__ void k_ntn(const float* __restrict__ ntn_w, const float* __restrict__ ntn_v,
                      const float* __restrict__ ntn_b) {
    int idx = threadIdx.x;           // 1024 = Bz*Kk
    int b = idx >> 4, k = idx & 15;
    const float* hi = g_h[0][b];
    const float* hj = g_h[1][b];
    const float* Wk = ntn_w + k * 256;
    float bil = 0.f;
#pragma unroll
    for (int d = 0; d < Dd; d++) {
        float t = 0.f;
#pragma unroll
        for (int e = 0; e < Dd; e++) t += Wk[d * Dd + e] * hj[e];
        bil += hi[d] * t;
    }
    float aff = 0.f;
#pragma unroll
    for (int d = 0; d < Dd; d++) aff += ntn_v[k * 32 + d] * hi[d];
#pragma unroll
    for (int d = 0; d < Dd; d++) aff += ntn_v[k * 32 + Dd + d] * hj[d];
    g_inter[b][k] = tanhf(bil + aff + ntn_b[k]);
}

// ---------------- similarity pass 1: min/max of fp32 dots -------------------
__global__ void k_minmax() {
    __shared__ float s_ui[64 * Dd];
    __shared__ float wmn[8], wmx[8];
    int b = blockIdx.x >> 3, chunk = blockIdx.x & 7;
    int tid = threadIdx.x;   // 256
    const float* ui = &g_u[0][b][chunk * 64][0];
    const float* uj = &g_u[1][b][0][0];
    for (int i = tid; i < 64 * Dd; i += 256) s_ui[i] = ui[i];
    __syncthreads();
    float mn = 3.4e38f, mx = -3.4e38f;
    for (int half = 0; half < 2; half++) {
        int col = half * 256 + tid;
        float ujr[Dd];
#pragma unroll
        for (int q = 0; q < 4; q++)
            *(float4*)&ujr[q * 4] = *(const float4*)&uj[col * Dd + q * 4];
        for (int rr = 0; rr < 64; rr++) {
            float dot = 0.f;
#pragma unroll
            for (int d = 0; d < Dd; d++) dot = __fmaf_rn(s_ui[rr * Dd + d], ujr[d], dot);
            mn = fminf(mn, dot); mx = fmaxf(mx, dot);
        }
    }
#pragma unroll
    for (int o = 16; o; o >>= 1) {
        mn = fminf(mn, __shfl_xor_sync(0xFFFFFFFFu, mn, o));
        mx = fmaxf(mx, __shfl_xor_sync(0xFFFFFFFFu, mx, o));
    }
    int warp = tid >> 5, lane = tid & 31;
    if (lane == 0) { wmn[warp] = mn; wmx[warp] = mx; }
    __syncthreads();
    if (tid == 0) {
        for (int w = 1; w < 8; w++) { mn = fminf(mn, wmn[w]); mx = fmaxf(mx, wmx[w]); }
        atomicMin(&g_mm[b][0], enc_f(mn));
        atomicMax(&g_mm[b][1], enc_f(mx));
    }
}

// ---------------- exact staircase bin thresholds via bit binary search ------
// Every stage (sigmoid, sub, reciprocal-multiply, exact *16, trunc) is weakly
// monotone in the fp32 dot, so thr_j := smallest fp32 d in [mnDot, mxDot]
// with bin(d) >= j gives: dot >= thr_j  <=>  bin(dot) >= j, exactly.
__global__ void k_thresh() {
    int t = threadIdx.x;            // 1024 = 64 graphs x 16 slots
    int b = t >> 4, j = t & 15;
    if (j == 0) return;             // j = 1..15
    float mnD = dec_f(g_mm[b][0]);
    float mxD = dec_f(g_mm[b][1]);
    float mnS = sig_ref(mnD);
    float mxS = sig_ref(mxD);
    float denom = fmaxf(__fsub_rn(mxS, mnS), 1e-12f);
    float recip = __fdiv_rn(1.0f, denom);   // XLA divide->reciprocal rewrite
    unsigned lo = enc_f(mnD), hi = enc_f(mxD);
    while (lo < hi) {
        unsigned mid = lo + ((hi - lo) >> 1);
        if (bin_of(sig_ref(dec_f(mid)), mnS, recip) >= j) hi = mid;
        else lo = mid + 1;
    }
    float thr = dec_f(lo);
    if (bin_of(sig_ref(thr), mnS, recip) < j) thr = __int_as_float(0x7F800000); // +inf
    g_thr[b][j - 1] = thr;
}

// ---------------- similarity pass 2: histogram over fp32 dots ---------------
__global__ void k_hist() {
    __shared__ float s_ui[64 * Dd];
    __shared__ int   s_hist[NBINS];
    __shared__ float s_thr[15];
    int b = blockIdx.x >> 3, chunk = blockIdx.x & 7;
    int tid = threadIdx.x;   // 256
    if (tid < NBINS) s_hist[tid] = 0;
    if (tid < 15) s_thr[tid] = g_thr[b][tid];
    const float* ui = &g_u[0][b][chunk * 64][0];
    const float* uj = &g_u[1][b][0][0];
    for (int i = tid; i < 64 * Dd; i += 256) s_ui[i] = ui[i];
    __syncthreads();
    float thr[15];
#pragma unroll
    for (int j = 0; j < 15; j++) thr[j] = s_thr[j];
    int lane = tid & 31;
    for (int half = 0; half < 2; half++) {
        int col = half * 256 + tid;
        float ujr[Dd];
#pragma unroll
        for (int q = 0; q < 4; q++)
            *(float4*)&ujr[q * 4] = *(const float4*)&uj[col * Dd + q * 4];
        for (int rr = 0; rr < 64; rr++) {
            float dot = 0.f;
#pragma unroll
            for (int d = 0; d < Dd; d++) dot = __fmaf_rn(s_ui[rr * Dd + d], ujr[d], dot);
            int ix = 0;
#pragma unroll
            for (int j = 0; j < 15; j++) ix += (dot >= thr[j]);
            unsigned msk = __match_any_sync(0xFFFFFFFFu, ix);
            if (lane == (__ffs(msk) - 1)) atomicAdd(&s_hist[ix], __popc(msk));
        }
    }
    __syncthreads();
    if (tid < NBINS) atomicAdd(&g_hist[b][tid], s_hist[tid]);
}

// ---------------- MLP head (fp32) ----------------
__global__ void k_mlp(const float* __restrict__ mw1, const float* __restrict__ mb1,
                      const float* __restrict__ mw2, const float* __restrict__ mb2,
                      const float* __restrict__ mw3, const float* __restrict__ mb3,
                      const float* __restrict__ mw4, const float* __restrict__ mb4,
                      const float* __restrict__ sw,  const float* __restrict__ sb,
                      float* __restrict__ out) {
    int b = threadIdx.x;
    if (b >= Bz) return;
    float f[32];
#pragma unroll
    for (int k = 0; k < 16; k++) f[k] = g_inter[b][k];
#pragma unroll
    for (int k = 0; k < 16; k++) f[16 + k] = (float)g_hist[b][k];
    float a1[32];
#pragma unroll
    for (int j = 0; j < 32; j++) {
        float s = mb1[j];
#pragma unroll
        for (int i = 0; i < 32; i++) s += f[i] * mw1[i * 32 + j];
        a1[j] = fmaxf(s, 0.f);
    }
    float a2[16];
#pragma unroll
    for (int j = 0; j < 16; j++) {
        float s = mb2[j];
#pragma unroll
        for (int i = 0; i < 32; i++) s += a1[i] * mw2[i * 16 + j];
        a2[j] = fmaxf(s, 0.f);
    }
    float a3[8];
#pragma unroll
    for (int j = 0; j < 8; j++) {
        float s = mb3[j];
#pragma unroll
        for (int i = 0; i < 16; i++) s += a2[i] * mw3[i * 8 + j];
        a3[j] = fmaxf(s, 0.f);
    }
    float a4[4];
#pragma unroll
    for (int j = 0; j < 4; j++) {
        float s = mb4[j];
#pragma unroll
        for (int i = 0; i < 8; i++) s += a3[i] * mw4[i * 4 + j];
        a4[j] = fmaxf(s, 0.f);
    }
    float sc = sb[0];
#pragma unroll
    for (int i = 0; i < 4; i++) sc += a4[i] * sw[i];
    out[b] = sc;
}

// ---------------- host launch ----------------
extern "C" void kernel_launch(void* const* d_in, const int* in_sizes, int n_in,
                              void* d_out, int out_size) {
    const float* x_i    = (const float*)d_in[0];
    const int*   ei     = (const int*)  d_in[1];
    const float* x_j    = (const float*)d_in[2];
    const int*   ej     = (const int*)  d_in[3];
    const float* w1     = (const float*)d_in[4];
    const float* b1     = (const float*)d_in[5];
    const float* w2     = (const float*)d_in[6];
    const float* b2     = (const float*)d_in[7];
    const float* w3     = (const float*)d_in[8];
    const float* b3     = (const float*)d_in[9];
    const float* attn_w = (const float*)d_in[10];
    const float* ntn_w  = (const float*)d_in[11];
    const float* ntn_v  = (const float*)d_in[12];
    const float* ntn_b  = (const float*)d_in[13];
    const float* mw1    = (const float*)d_in[14];
    const float* mb1    = (const float*)d_in[15];
    const float* mw2    = (const float*)d_in[16];
    const float* mb2    = (const float*)d_in[17];
    const float* mw3    = (const float*)d_in[18];
    const float* mb3    = (const float*)d_in[19];
    const float* mw4    = (const float*)d_in[20];
    const float* mb4    = (const float*)d_in[21];
    const float* sw     = (const float*)d_in[22];
    const float* sb     = (const float*)d_in[23];
    float* out = (float*)d_out;

    void *pA = nullptr, *pB = nullptr, *pU = nullptr;
    cudaGetSymbolAddress(&pA, g_bufA);
    cudaGetSymbolAddress(&pB, g_bufB);
    cudaGetSymbolAddress(&pU, g_u);
    float* bufA  = (float*)pA;
    float* bufB  = (float*)pB;
    float* ubase = (float*)pU;

    const int SM64 = Nn * 64 * 4 + Nn * 4;   // 133120
    const int SM32 = Nn * 32 * 4 + Nn * 4;   //  67584
    const int SM16 = Nn * 16 * 4 + Nn * 4;   //  34816
    cudaFuncSetAttribute(k_spmm<64, true>,  cudaFuncAttributeMaxDynamicSharedMemorySize, SM64);
    cudaFuncSetAttribute(k_spmm<32, true>,  cudaFuncAttributeMaxDynamicSharedMemorySize, SM32);
    cudaFuncSetAttribute(k_spmm<16, false>, cudaFuncAttributeMaxDynamicSharedMemorySize, SM16);

    k_init<<<2048, 512>>>();
    k_scatter<<<(2 * Bz * Ez + 2 * Bz * Nn + 255) / 256, 256>>>(ei, ej);
    k_dinv<<<(2 * Bz * Nn) / 256, 256>>>();

    for (int s = 0; s < 2; s++) {
        const float* x = s ? x_j : x_i;
        float* bA = bufA  + (size_t)s * Bz * Nn * 64;
        float* bB = bufB  + (size_t)s * Bz * Nn * 64;
        float* u  = ubase + (size_t)s * Bz * Nn * Dd;
        k_gemm<128, 64><<<(Bz * Nn) / 16, 128>>>(x, w1, bA);
        k_spmm<64, true><<<Bz, 512, SM64>>>(s, bA, b1, bB);
        k_gemm<64, 32><<<(Bz * Nn) / 16, 64>>>(bB, w2, bA);
        k_spmm<32, true><<<Bz, 512, SM32>>>(s, bA, b2, bB);
        k_gemm<32, 16><<<(Bz * Nn) / 16, 32>>>(bB, w3, bA);
        k_spmm<16, false><<<Bz, 512, SM16>>>(s, bA, b3, u);
    }

    k_attpool<<<2 * Bz, 256>>>(attn_w);
    k_ntn<<<1, 1024>>>(ntn_w, ntn_v, ntn_b);
    k_minmax<<<Bz * 8, 256>>>();
    k_thresh<<<1, 1024>>>();
    k_hist<<<Bz * 8, 256>>>();
    k_mlp<<<1, 64>>>(mw1, mb1, mw2, mb2, mw3, mb3, mw4, mb4, sw, sb, out);

    (void)in_sizes; (void)n_in; (void)out_size;
}

// round 16
// speedup vs baseline: 1.4380x; 1.4380x over previous
#include <cuda_runtime.h>
#include <math.h>

#define Bz   64
#define Nn   512
#define Ez   8192
#define NWd  16      // bitmap words per row (512/32)
#define Dd   16
#define Kk   16
#define NBINS 16

// ---------------- scratch (static device allocations) ----------------
__device__ unsigned g_bm[2][Bz][Nn][NWd];        // adjacency bitmaps (4 MB)
__device__ float    g_dinv[2][Bz][Nn];           // D^-1/2
__device__ int      g_deg[2][Bz][Nn];            // row degrees
__device__ unsigned short g_idx[2][Bz][Nn][512]; // per-row column lists (67 MB)
__device__ float    g_bufA[2][Bz * Nn * 64];     // ping  (16.8 MB)
__device__ float    g_bufB[2][Bz * Nn * 64];     // pong  (16.8 MB)
__device__ float    g_u[2][Bz][Nn][Dd];          // final node embeddings
__device__ float    g_h[2][Bz][Dd];              // pooled graph embeddings
__device__ unsigned g_mm[Bz][2];                 // encoded {min,max} of raw dots
__device__ float    g_thr[Bz][16];               // 15 bin thresholds in dot space
__device__ int      g_hist[Bz][NBINS];
__device__ float    g_inter[Bz][Kk];             // NTN interaction

// monotone float <-> uint mapping for atomicMin/Max over signed floats
__device__ __forceinline__ unsigned enc_f(float f) {
    unsigned u = __float_as_uint(f);
    return (u & 0x80000000u) ? ~u : (u | 0x80000000u);
}
__device__ __forceinline__ float dec_f(unsigned e) {
    return (e & 0x80000000u) ? __uint_as_float(e & 0x7FFFFFFFu)
                             : __uint_as_float(~e);
}

// Reference fp32 sigmoid, exp form with correctly-rounded exp:
// s = RN(1 / RN(1 + RN(e^-x))). (Frozen — verified rel_err 4.4e-6.)
__device__ __forceinline__ float sig_ref(float x) {
    float e = (float)exp(-(double)x);
    return __fdiv_rn(1.0f, __fadd_rn(1.0f, e));
}

// Reference binning with XLA's divide->reciprocal-multiply rewrite (frozen):
__device__ __forceinline__ int bin_of(float s, float mn, float recip) {
    float t = __fsub_rn(s, mn);
    float q = __fmul_rn(t, recip);
    float v = q * 16.0f;              // exact power-of-2 scaling
    int ix = (int)v;
    return ix < 0 ? 0 : (ix > 15 ? 15 : ix);
}

// ---------------- init: zero bitmaps + hist, init min/max ----------------
__global__ void k_init() {
    int idx = blockIdx.x * blockDim.x + threadIdx.x;
    unsigned* bm = &g_bm[0][0][0][0];
    const int total = 2 * Bz * Nn * NWd;   // 1,048,576
    for (int i = idx; i < total; i += gridDim.x * blockDim.x) bm[i] = 0u;
    if (idx < Bz * NBINS) ((int*)g_hist)[idx] = 0;
    if (idx < Bz) { g_mm[idx][0] = 0xFFFFFFFFu; g_mm[idx][1] = 0u; }
}

// ---------------- scatter edges + self loops into bitmaps ----------------
__global__ void k_scatter(const int* __restrict__ ei, const int* __restrict__ ej) {
    int idx = blockIdx.x * blockDim.x + threadIdx.x;
    const int TE = 2 * Bz * Ez;
    if (idx < TE) {
        int side = idx / (Bz * Ez);
        int rem  = idx - side * (Bz * Ez);
        int b = rem / Ez, e = rem - (rem / Ez) * Ez;
        const int* p = side ? ej : ei;
        int r = p[(size_t)b * 2 * Ez + e];
        int c = p[(size_t)b * 2 * Ez + Ez + e];
        atomicOr(&g_bm[side][b][r][c >> 5], 1u << (c & 31));
    } else {
        int j = idx - TE;
        if (j < 2 * Bz * Nn) {
            int side = j / (Bz * Nn);
            int rem  = j - side * (Bz * Nn);
            int b = rem >> 9, n = rem & 511;
            atomicOr(&g_bm[side][b][n][n >> 5], 1u << (n & 31));
        }
    }
}

// ------- degrees -> D^-1/2 (CR via double) + ascending column lists --------
__global__ void k_dinv() {
    int idx = blockIdx.x * blockDim.x + threadIdx.x;  // 2*Bz*Nn threads
    int side = idx >> 15;
    int rem  = idx & 32767;
    int b = rem >> 9, n = rem & 511;
    unsigned short* il = g_idx[side][b][n];
    int d = 0;
#pragma unroll
    for (int w = 0; w < NWd; w++) {
        unsigned bits = g_bm[side][b][n][w];
        while (bits) {
            int t = __ffs(bits) - 1; bits &= bits - 1;
            il[d++] = (unsigned short)((w << 5) + t);
        }
    }
    g_deg[side][b][n]  = d;
    g_dinv[side][b][n] = (float)(1.0 / sqrt((double)d));   // d >= 1
}

// ---------------- dense GEMM v2: Y[M,NC] = X[M,KK] @ W[KK,NC] --------------
// 256 threads, RB-row tile; thread = RT rows x 2 cols. Per-output ascending-k
// sequential FFMA chain — bitwise identical to the verified r15 kernel.
template<int KK, int NC, int RB>
__global__ void __launch_bounds__(256) k_gemm2(const float* __restrict__ X,
                                               const float* __restrict__ W,
                                               float* __restrict__ Y) {
    constexpr int CP = NC / 2;        // column pairs
    constexpr int RG = 256 / CP;      // row groups
    constexpr int RT = RB / RG;       // rows per thread
    extern __shared__ float gsm[];
    float* Xs = gsm;                  // RB*KK
    float* Ws = gsm + RB * KK;        // KK*NC
    int tid = threadIdx.x;
    int r0  = blockIdx.x * RB;
    for (int i = tid; i < KK * NC / 4; i += 256)
        ((float4*)Ws)[i] = ((const float4*)W)[i];
    const float* xsrc = X + (size_t)r0 * KK;
    for (int i = tid; i < RB * KK / 4; i += 256)
        ((float4*)Xs)[i] = ((const float4*)xsrc)[i];
    __syncthreads();
    int cp = tid % CP, rg = tid / CP;
    int col = cp * 2, rbase = rg * RT;
    float2 acc[RT];
#pragma unroll
    for (int i = 0; i < RT; i++) acc[i] = make_float2(0.f, 0.f);
#pragma unroll 4
    for (int k = 0; k < KK; k++) {
        float2 wv = *(const float2*)&Ws[k * NC + col];
#pragma unroll
        for (int i = 0; i < RT; i++) {
            float xv = Xs[(rbase + i) * KK + k];
            acc[i].x += xv * wv.x;
            acc[i].y += xv * wv.y;
        }
    }
#pragma unroll
    for (int i = 0; i < RT; i++)
        *(float2*)&Y[(size_t)(r0 + rbase + i) * NC + col] = acc[i];
}

// ---------------- SpMM v3: Y = act(D^-1/2 (A+I) D^-1/2 @ X + bias) ---------
// Index-list driven (no serial bit-scan dependency), 2 blocks per graph
// (row split). Ascending-c accumulation — bitwise identical to r15.
template<int FO, bool RELU>
__global__ void k_spmm(int side, const float* __restrict__ Xin,
                       const float* __restrict__ bias, float* __restrict__ Y) {
    extern __shared__ float sm[];
    float* sx = sm;              // Nn*FO
    float* sd = sm + Nn * FO;    // Nn
    int bb   = blockIdx.x;
    int b    = bb >> 1;
    int half = bb & 1;
    int tid = threadIdx.x;       // 512
    const float* xin = Xin + (size_t)b * Nn * FO;
    for (int i = tid; i < Nn * FO / 4; i += 512)
        ((float4*)sx)[i] = ((const float4*)xin)[i];
    for (int i = tid; i < Nn; i += 512) sd[i] = g_dinv[side][b][i];
    __syncthreads();
    int warp = tid >> 5, lane = tid & 31;
    bool act = (lane * 2 < FO);
    int rend = half * 256 + 256;
    for (int r = half * 256 + warp; r < rend; r += 16) {
        int deg = g_deg[side][b][r];
        const unsigned short* il = g_idx[side][b][r];
        float dr = sd[r];
        float2 acc = make_float2(0.f, 0.f);
        int i = 0;
        for (; i + 8 <= deg; i += 8) {
            uint4 pk = *(const uint4*)&il[i];
            unsigned cs[8];
            cs[0] = pk.x & 0xFFFFu; cs[1] = pk.x >> 16;
            cs[2] = pk.y & 0xFFFFu; cs[3] = pk.y >> 16;
            cs[4] = pk.z & 0xFFFFu; cs[5] = pk.z >> 16;
            cs[6] = pk.w & 0xFFFFu; cs[7] = pk.w >> 16;
#pragma unroll
            for (int j = 0; j < 8; j++) {
                unsigned c = cs[j];
                float coef = __fmul_rn(dr, sd[c]);
                if (act) {
                    float2 v = *(const float2*)&sx[c * FO + lane * 2];
                    acc.x += coef * v.x; acc.y += coef * v.y;
                }
            }
        }
        for (; i < deg; i++) {
            unsigned c = il[i];
            float coef = __fmul_rn(dr, sd[c]);
            if (act) {
                float2 v = *(const float2*)&sx[c * FO + lane * 2];
                acc.x += coef * v.x; acc.y += coef * v.y;
            }
        }
        if (act) {
            float vx = acc.x + bias[lane * 2];
            float vy = acc.y + bias[lane * 2 + 1];
            if (RELU) { vx = fmaxf(vx, 0.f); vy = fmaxf(vy, 0.f); }
            *(float2*)&Y[((size_t)b * Nn + r) * FO + lane * 2] = make_float2(vx, vy);
        }
    }
}

// ---------------- attention pooling (unchanged from r15) --------------------
__global__ void k_attpool(const float* __restrict__ attn_w) {
    __shared__ float s_mean[Dd], s_c[Dd], s_h[Dd];
    int side = blockIdx.x >> 6;
    int b    = blockIdx.x & 63;
    int tid  = threadIdx.x;          // 256
    if (tid < Dd) { s_mean[tid] = 0.f; s_h[tid] = 0.f; }
    __syncthreads();
    const float* u = &g_u[side][b][0][0];
    float loc[Dd];
#pragma unroll
    for (int d = 0; d < Dd; d++) loc[d] = u[tid * Dd + d] + u[(tid + 256) * Dd + d];
#pragma unroll
    for (int d = 0; d < Dd; d++) atomicAdd(&s_mean[d], loc[d]);
    __syncthreads();
    if (tid < Dd) {
        float acc = 0.f;
#pragma unroll
        for (int e = 0; e < Dd; e++)
            acc += (s_mean[e] * (1.f / (float)Nn)) * attn_w[e * Dd + tid];
        s_c[tid] = tanhf(acc);
    }
    __syncthreads();
    for (int pass = 0; pass < 2; pass++) {
        int n = tid + pass * 256;
        float uv[Dd];
        float dot = 0.f;
#pragma unroll
        for (int d = 0; d < Dd; d++) { uv[d] = u[n * Dd + d]; dot += uv[d] * s_c[d]; }
        float s = 1.f / (1.f + expf(-dot));
#pragma unroll
        for (int d = 0; d < Dd; d++) atomicAdd(&s_h[d], s * uv[d]);
    }
    __syncthreads();
    if (tid < Dd) g_h[side][b][tid] = s_h[tid];
}

// ---------------- NTN (unchanged) ----------------
__global__ void k_ntn(const float* __restrict__ ntn_w, const float* __restrict__ ntn_v,
                      const float* __restrict__ ntn_b) {
    int idx = threadIdx.x;           // 1024 = Bz*Kk
    int b = idx >> 4, k = idx & 15;
    const float* hi = g_h[0][b];
    const float* hj = g_h[1][b];
    const float* Wk = ntn_w + k * 256;
    float bil = 0.f;
#pragma unroll
    for (int d = 0; d < Dd; d++) {
        float t = 0.f;
#pragma unroll
        for (int e = 0; e < Dd; e++) t += Wk[d * Dd + e] * hj[e];
        bil += hi[d] * t;
    }
    float aff = 0.f;
#pragma unroll
    for (int d = 0; d < Dd; d++) aff += ntn_v[k * 32 + d] * hi[d];
#pragma unroll
    for (int d = 0; d < Dd; d++) aff += ntn_v[k * 32 + Dd + d] * hj[d];
    g_inter[b][k] = tanhf(bil + aff + ntn_b[k]);
}

// ---------------- similarity pass 1: min/max of fp32 dots (unchanged) ------
__global__ void k_minmax() {
    __shared__ float s_ui[64 * Dd];
    __shared__ float wmn[8], wmx[8];
    int b = blockIdx.x >> 3, chunk = blockIdx.x & 7;
    int tid = threadIdx.x;   // 256
    const float* ui = &g_u[0][b][chunk * 64][0];
    const float* uj = &g_u[1][b][0][0];
    for (int i = tid; i < 64 * Dd; i += 256) s_ui[i] = ui[i];
    __syncthreads();
    float mn = 3.4e38f, mx = -3.4e38f;
    for (int half = 0; half < 2; half++) {
        int col = half * 256 + tid;
        float ujr[Dd];
#pragma unroll
        for (int q = 0; q < 4; q++)
            *(float4*)&ujr[q * 4] = *(const float4*)&uj[col * Dd + q * 4];
        for (int rr = 0; rr < 64; rr++) {
            float dot = 0.f;
#pragma unroll
            for (int d = 0; d < Dd; d++) dot = __fmaf_rn(s_ui[rr * Dd + d], ujr[d], dot);
            mn = fminf(mn, dot); mx = fmaxf(mx, dot);
        }
    }
#pragma unroll
    for (int o = 16; o; o >>= 1) {
        mn = fminf(mn, __shfl_xor_sync(0xFFFFFFFFu, mn, o));
        mx = fmaxf(mx, __shfl_xor_sync(0xFFFFFFFFu, mx, o));
    }
    int warp = tid >> 5, lane = tid & 31;
    if (lane == 0) { wmn[warp] = mn; wmx[warp] = mx; }
    __syncthreads();
    if (tid == 0) {
        for (int w = 1; w < 8; w++) { mn = fminf(mn, wmn[w]); mx = fmaxf(mx, wmx[w]); }
        atomicMin(&g_mm[b][0], enc_f(mn));
        atomicMax(&g_mm[b][1], enc_f(mx));
    }
}

// ---------------- exact staircase thresholds (unchanged, frozen) ------------
__global__ void k_thresh() {
    int t = threadIdx.x;            // 1024 = 64 graphs x 16 slots
    int b = t >> 4, j = t & 15;
    if (j == 0) return;             // j = 1..15
    float mnD = dec_f(g_mm[b][0]);
    float mxD = dec_f(g_mm[b][1]);
    float mnS = sig_ref(mnD);
    float mxS = sig_ref(mxD);
    float denom = fmaxf(__fsub_rn(mxS, mnS), 1e-12f);
    float recip = __fdiv_rn(1.0f, denom);   // XLA divide->reciprocal rewrite
    unsigned lo = enc_f(mnD), hi = enc_f(mxD);
    while (lo < hi) {
        unsigned mid = lo + ((hi - lo) >> 1);
        if (bin_of(sig_ref(dec_f(mid)), mnS, recip) >= j) hi = mid;
        else lo = mid + 1;
    }
    float thr = dec_f(lo);
    if (bin_of(sig_ref(thr), mnS, recip) < j) thr = __int_as_float(0x7F800000); // +inf
    g_thr[b][j - 1] = thr;
}

// ---------------- similarity pass 2: histogram (unchanged) ------------------
__global__ void k_hist() {
    __shared__ float s_ui[64 * Dd];
    __shared__ int   s_hist[NBINS];
    __shared__ float s_thr[15];
    int b = blockIdx.x >> 3, chunk = blockIdx.x & 7;
    int tid = threadIdx.x;   // 256
    if (tid < NBINS) s_hist[tid] = 0;
    if (tid < 15) s_thr[tid] = g_thr[b][tid];
    const float* ui = &g_u[0][b][chunk * 64][0];
    const float* uj = &g_u[1][b][0][0];
    for (int i = tid; i < 64 * Dd; i += 256) s_ui[i] = ui[i];
    __syncthreads();
    float thr[15];
#pragma unroll
    for (int j = 0; j < 15; j++) thr[j] = s_thr[j];
    int lane = tid & 31;
    for (int half = 0; half < 2; half++) {
        int col = half * 256 + tid;
        float ujr[Dd];
#pragma unroll
        for (int q = 0; q < 4; q++)
            *(float4*)&ujr[q * 4] = *(const float4*)&uj[col * Dd + q * 4];
        for (int rr = 0; rr < 64; rr++) {
            float dot = 0.f;
#pragma unroll
            for (int d = 0; d < Dd; d++) dot = __fmaf_rn(s_ui[rr * Dd + d], ujr[d], dot);
            int ix = 0;
#pragma unroll
            for (int j = 0; j < 15; j++) ix += (dot >= thr[j]);
            unsigned msk = __match_any_sync(0xFFFFFFFFu, ix);
            if (lane == (__ffs(msk) - 1)) atomicAdd(&s_hist[ix], __popc(msk));
        }
    }
    __syncthreads();
    if (tid < NBINS) atomicAdd(&g_hist[b][tid], s_hist[tid]);
}

// ---------------- MLP head (unchanged) ----------------
__global__ void k_mlp(const float* __restrict__ mw1, const float* __restrict__ mb1,
                      const float* __restrict__ mw2, const float* __restrict__ mb2,
                      const float* __restrict__ mw3, const float* __restrict__ mb3,
                      const float* __restrict__ mw4, const float* __restrict__ mb4,
                      const float* __restrict__ sw,  const float* __restrict__ sb,
                      float* __restrict__ out) {
    int b = threadIdx.x;
    if (b >= Bz) return;
    float f[32];
#pragma unroll
    for (int k = 0; k < 16; k++) f[k] = g_inter[b][k];
#pragma unroll
    for (int k = 0; k < 16; k++) f[16 + k] = (float)g_hist[b][k];
    float a1[32];
#pragma unroll
    for (int j = 0; j < 32; j++) {
        float s = mb1[j];
#pragma unroll
        for (int i = 0; i < 32; i++) s += f[i] * mw1[i * 32 + j];
        a1[j] = fmaxf(s, 0.f);
    }
    float a2[16];
#pragma unroll
    for (int j = 0; j < 16; j++) {
        float s = mb2[j];
#pragma unroll
        for (int i = 0; i < 32; i++) s += a1[i] * mw2[i * 16 + j];
        a2[j] = fmaxf(s, 0.f);
    }
    float a3[8];
#pragma unroll
    for (int j = 0; j < 8; j++) {
        float s = mb3[j];
#pragma unroll
        for (int i = 0; i < 16; i++) s += a2[i] * mw3[i * 8 + j];
        a3[j] = fmaxf(s, 0.f);
    }
    float a4[4];
#pragma unroll
    for (int j = 0; j < 4; j++) {
        float s = mb4[j];
#pragma unroll
        for (int i = 0; i < 8; i++) s += a3[i] * mw4[i * 4 + j];
        a4[j] = fmaxf(s, 0.f);
    }
    float sc = sb[0];
#pragma unroll
    for (int i = 0; i < 4; i++) sc += a4[i] * sw[i];
    out[b] = sc;
}

// ---------------- host launch ----------------
extern "C" void kernel_launch(void* const* d_in, const int* in_sizes, int n_in,
                              void* d_out, int out_size) {
    const float* x_i    = (const float*)d_in[0];
    const int*   ei     = (const int*)  d_in[1];
    const float* x_j    = (const float*)d_in[2];
    const int*   ej     = (const int*)  d_in[3];
    const float* w1     = (const float*)d_in[4];
    const float* b1     = (const float*)d_in[5];
    const float* w2     = (const float*)d_in[6];
    const float* b2     = (const float*)d_in[7];
    const float* w3     = (const float*)d_in[8];
    const float* b3     = (const float*)d_in[9];
    const float* attn_w = (const float*)d_in[10];
    const float* ntn_w  = (const float*)d_in[11];
    const float* ntn_v  = (const float*)d_in[12];
    const float* ntn_b  = (const float*)d_in[13];
    const float* mw1    = (const float*)d_in[14];
    const float* mb1    = (const float*)d_in[15];
    const float* mw2    = (const float*)d_in[16];
    const float* mb2    = (const float*)d_in[17];
    const float* mw3    = (const float*)d_in[18];
    const float* mb3    = (const float*)d_in[19];
    const float* mw4    = (const float*)d_in[20];
    const float* mb4    = (const float*)d_in[21];
    const float* sw     = (const float*)d_in[22];
    const float* sb     = (const float*)d_in[23];
    float* out = (float*)d_out;

    void *pA = nullptr, *pB = nullptr, *pU = nullptr;
    cudaGetSymbolAddress(&pA, g_bufA);
    cudaGetSymbolAddress(&pB, g_bufB);
    cudaGetSymbolAddress(&pU, g_u);
    float* bufA  = (float*)pA;
    float* bufB  = (float*)pB;
    float* ubase = (float*)pU;

    const int SM64 = Nn * 64 * 4 + Nn * 4;   // 133120
    const int SM32 = Nn * 32 * 4 + Nn * 4;   //  67584
    const int SM16 = Nn * 16 * 4 + Nn * 4;   //  34816
    cudaFuncSetAttribute(k_spmm<64, true>,  cudaFuncAttributeMaxDynamicSharedMemorySize, SM64);
    cudaFuncSetAttribute(k_spmm<32, true>,  cudaFuncAttributeMaxDynamicSharedMemorySize, SM32);
    cudaFuncSetAttribute(k_spmm<16, false>, cudaFuncAttributeMaxDynamicSharedMemorySize, SM16);

    const int GS1 = (64 * 128 + 128 * 64) * 4;   // 65536
    const int GS2 = (64 * 64  + 64 * 32)  * 4;   // 24576
    const int GS3 = (128 * 32 + 32 * 16)  * 4;   // 18432
    cudaFuncSetAttribute(k_gemm2<128, 64, 64>, cudaFuncAttributeMaxDynamicSharedMemorySize, GS1);

    k_init<<<2048, 512>>>();
    k_scatter<<<(2 * Bz * Ez + 2 * Bz * Nn + 255) / 256, 256>>>(ei, ej);
    k_dinv<<<(2 * Bz * Nn) / 256, 256>>>();

    for (int s = 0; s < 2; s++) {
        const float* x = s ? x_j : x_i;
        float* bA = bufA  + (size_t)s * Bz * Nn * 64;
        float* bB = bufB  + (size_t)s * Bz * Nn * 64;
        float* u  = ubase + (size_t)s * Bz * Nn * Dd;
        k_gemm2<128, 64, 64><<<(Bz * Nn) / 64, 256, GS1>>>(x, w1, bA);
        k_spmm<64, true><<<Bz * 2, 512, SM64>>>(s, bA, b1, bB);
        k_gemm2<64, 32, 64><<<(Bz * Nn) / 64, 256, GS2>>>(bB, w2, bA);
        k_spmm<32, true><<<Bz * 2, 512, SM32>>>(s, bA, b2, bB);
        k_gemm2<32, 16, 128><<<(Bz * Nn) / 128, 256, GS3>>>(bB, w3, bA);
        k_spmm<16, false><<<Bz * 2, 512, SM16>>>(s, bA, b3, u);
    }

    k_attpool<<<2 * Bz, 256>>>(attn_w);
    k_ntn<<<1, 1024>>>(ntn_w, ntn_v, ntn_b);
    k_minmax<<<Bz * 8, 256>>>();
    k_thresh<<<1, 1024>>>();
    k_hist<<<Bz * 8, 256>>>();
    k_mlp<<<1, 64>>>(mw1, mb1, mw2, mb2, mw3, mb3, mw4, mb4, sw, sb, out);

    (void)in_sizes; (void)n_in; (void)out_size;
}